// round 1
// baseline (speedup 1.0000x reference)
#include <cuda_runtime.h>
#include <math.h>

#define NN 8192
#define LL 512
#define KK 30

// ---------------- device scratch (no allocations allowed) ----------------
__device__ int   g_mask_u8;          // 1 if masks are 1-byte bools, 0 if int32
__device__ int   g_knn [NN * KK];    // neighbor global index
__device__ float g_dist[NN * KK];    // neighbor distance
__device__ float g_Psrc[NN * 128];   // emb0 @ W_alpha[0:35]
__device__ float g_Ptgt[NN * 128];   // emb0 @ W_alpha[35:70]
__device__ float g_Vnode[NN * 256];  // emb(4x35) @ W_v  -> [4][64]
__device__ float g_posA[1023 * 128]; // pos_emb(delta) @ W_alpha[86:102]

// ---------------- kernel 0: pos-emb table + mask layout probe ----------------
__global__ void k_posA(const float* __restrict__ Wa,
                       const unsigned char* __restrict__ xm)
{
    int t = threadIdx.x;
    if (blockIdx.x == 0 && t == 0) {
        // If masks are int32 (little-endian 0/1), every byte at index i with
        // (i & 3) != 0 is zero. If 1-byte bools, ~half of them are 1.
        int any = 0;
        for (int i = 1; i < 256; i++)
            if (i & 3) any |= (int)xm[i];
        g_mask_u8 = any ? 1 : 0;
    }
    __shared__ float trig[16];
    int dd = blockIdx.x;               // delta + 511
    float delta = (float)(dd - 511);
    if (t < 8) {
        // freq_j = exp(2j * (-ln(10000)/16))
        float freq = expf(-(float)(2 * t) * (9.210340371976184f / 16.0f));
        float ang = delta * freq;
        trig[t]     = cosf(ang);
        trig[8 + t] = sinf(ang);
    }
    __syncthreads();
    float s = 0.f;
#pragma unroll
    for (int j = 0; j < 8; j++) {
        s = fmaf(trig[j],     Wa[(86 + j) * 128 + t], s);  // cos rows
        s = fmaf(trig[8 + j], Wa[(94 + j) * 128 + t], s);  // sin rows
    }
    g_posA[dd * 128 + t] = s;
}

// ---------------- kernel 1: per-chain brute-force kNN (warp per target) -----
__global__ void k_knn(const float* __restrict__ trans)
{
    __shared__ float sx[LL], sy[LL], sz[LL];
    int t = threadIdx.x;
    int g0 = blockIdx.x * 4;          // 4 targets per block (4 warps)
    int chain = g0 >> 9;
    int base = chain << 9;
    for (int i = t; i < LL; i += 128) {
        const float* p = trans + (size_t)(base + i) * 3;
        sx[i] = p[0]; sy[i] = p[1]; sz[i] = p[2];
    }
    __syncthreads();
    int warp = t >> 5, lane = t & 31;
    int tgt = g0 + warp;
    int tl = tgt & 511;
    float px = sx[tl], py = sy[tl], pz = sz[tl];
    float d[16];
#pragma unroll
    for (int q = 0; q < 16; q++) {
        int c = lane + (q << 5);
        float dx = sx[c] - px, dy = sy[c] - py, dz = sz[c] - pz;
        float d2 = dx * dx + dy * dy + dz * dz;
        d[q] = (c == tl) ? 1e30f : d2;   // exclude self
    }
    for (int it = 0; it < KK; it++) {
        float bv = d[0]; int bq = 0;
#pragma unroll
        for (int q = 1; q < 16; q++)
            if (d[q] < bv) { bv = d[q]; bq = q; }
        int bi = lane + (bq << 5);
#pragma unroll
        for (int off = 16; off > 0; off >>= 1) {
            float ov = __shfl_down_sync(0xffffffffu, bv, off);
            int   oi = __shfl_down_sync(0xffffffffu, bi, off);
            if (ov < bv || (ov == bv && oi < bi)) { bv = ov; bi = oi; }
        }
        bv = __shfl_sync(0xffffffffu, bv, 0);
        bi = __shfl_sync(0xffffffffu, bi, 0);
        if (lane == (bi & 31)) {
            int wq = bi >> 5;
#pragma unroll
            for (int q = 0; q < 16; q++)
                if (q == wq) d[q] = 1e30f;
        }
        if (lane == 0) {
            g_knn [tgt * KK + it] = base + bi;
            g_dist[tgt * KK + it] = sqrtf(bv);
        }
    }
}

// ---------------- kernel 2: per-node precompute (8 nodes / block) -----------
__global__ void k_node(const float* __restrict__ rots,
                       const float* __restrict__ node_emb,
                       const unsigned char* __restrict__ xm,
                       const unsigned char* __restrict__ nm,
                       const float* __restrict__ Wa,
                       const float* __restrict__ Wv)
{
    __shared__ float sA[70 * 128];        // W_alpha rows 0..69 (src | tgt)
    __shared__ float semb[8][4][36];      // fused emb rows, padded
    int t = threadIdx.x;
    for (int i = t; i < 70 * 128; i += 128) sA[i] = Wa[i];
    int n0 = blockIdx.x * 8;
    int u8 = g_mask_u8;
    for (int m = 0; m < 8; m++) {
        int n = n0 + m;
        int r = t >> 5, c = t & 31;
        semb[m][r][c] = node_emb[n * 128 + t];
        if (t == 0) {
            const float* R = rots + n * 9;
            // frame_atoms[a][i] = rots[i] . IDEAL_BB[a]; IDEAL_BB z-col = 0
            const float bx0 = -0.525f, by0 = 1.363f;  // atom N
            const float bx2 = 1.526f;                 // atom C  (CA = 0)
#pragma unroll
            for (int i = 0; i < 3; i++) {
                float r0 = R[i * 3 + 0], r1 = R[i * 3 + 1];
                semb[m][1 + i][32 + 0] = r0 * bx0 + r1 * by0;
                semb[m][1 + i][32 + 1] = 0.f;
                semb[m][1 + i][32 + 2] = r0 * bx2;
            }
            int xv = u8 ? (int)xm[n] : (int)xm[n * 4];
            int nv = u8 ? (int)nm[n] : (int)nm[n * 4];
            semb[m][0][32] = 0.f;
            semb[m][0][33] = 0.f;
            semb[m][0][34] = (nv && !xv) ? 1.f : 0.f;   // editable flag
        }
    }
    __syncthreads();
    // Psrc / Ptgt : emb row0 @ (A_src | A_tgt)
    float accS[8], accT[8];
#pragma unroll
    for (int m = 0; m < 8; m++) { accS[m] = 0.f; accT[m] = 0.f; }
    for (int ch = 0; ch < 35; ch++) {
        float as = sA[ch * 128 + t];
        float at = sA[(35 + ch) * 128 + t];
#pragma unroll
        for (int m = 0; m < 8; m++) {
            float e0 = semb[m][0][ch];
            accS[m] = fmaf(e0, as, accS[m]);
            accT[m] = fmaf(e0, at, accT[m]);
        }
    }
#pragma unroll
    for (int m = 0; m < 8; m++) {
        g_Psrc[(n0 + m) * 128 + t] = accS[m];
        g_Ptgt[(n0 + m) * 128 + t] = accT[m];
    }
    // Vnode : emb[4][35] @ W_v[35][64]  (rotation cancels -> per-node)
    float v0[8], v1[8];
#pragma unroll
    for (int m = 0; m < 8; m++) { v0[m] = 0.f; v1[m] = 0.f; }
    int c = t & 63, r0 = t >> 6;
    for (int ch = 0; ch < 35; ch++) {
        float w = Wv[ch * 64 + c];
#pragma unroll
        for (int m = 0; m < 8; m++) {
            v0[m] = fmaf(semb[m][r0][ch],     w, v0[m]);
            v1[m] = fmaf(semb[m][r0 + 2][ch], w, v1[m]);
        }
    }
#pragma unroll
    for (int m = 0; m < 8; m++) {
        g_Vnode[(n0 + m) * 256 + t]       = v0[m];
        g_Vnode[(n0 + m) * 256 + 128 + t] = v1[m];
    }
}

// ---------------- kernel 3: attention + aggregation + output FFN ------------
__global__ void k_main(const float* __restrict__ Wa,
                       const float* __restrict__ avec,
                       const float* __restrict__ Wo,
                       const float* __restrict__ Wg,
                       const float* __restrict__ W2,
                       float* __restrict__ out)
{
    __shared__ float s_rbf[KK][16];
    __shared__ float s_logit[KK][8];
    __shared__ float s_alpha[KK][8];
    __shared__ int   s_src[KK];
    __shared__ float s_dist[KK];
    __shared__ float s_valid[KK];
    __shared__ float s_agg[256];
    __shared__ float s_y[128];
    __shared__ float s_gate[32];

    int n = blockIdx.x, t = threadIdx.x;
    if (t < KK) {
        int s = g_knn[n * KK + t];
        float d = g_dist[n * KK + t];
        s_src[t] = s;
        s_dist[t] = d;
        s_valid[t] = (isfinite(d) && d > 1e-3f) ? 1.f : 0.f;
    }
    float ptgt = g_Ptgt[n * 128 + t];
    float av = avec[t];                 // a_vec flat: t = h*16+k
    float arb[16];
#pragma unroll
    for (int j = 0; j < 16; j++) arb[j] = Wa[(70 + j) * 128 + t];  // RBF rows
    __syncthreads();
    // RBF features: mu = linspace(0,20,16), sigma = 1.25
    for (int i = t; i < KK * 16; i += 128) {
        int e = i >> 4, j = i & 15;
        float x = (s_dist[e] - (float)j * (20.0f / 15.0f)) * 0.8f;
        s_rbf[e][j] = __expf(-x * x);
    }
    __syncthreads();
    // logits
    for (int e = 0; e < KK; e++) {
        int src = s_src[e];
        float acc = ptgt + g_Psrc[src * 128 + t]
                         + g_posA[(src - n + 511) * 128 + t];
#pragma unroll
        for (int j = 0; j < 16; j++) acc = fmaf(s_rbf[e][j], arb[j], acc);
        float hd = acc / (1.f + __expf(-acc));       // silu
        float p = hd * av;
        p += __shfl_xor_sync(0xffffffffu, p, 8);
        p += __shfl_xor_sync(0xffffffffu, p, 4);
        p += __shfl_xor_sync(0xffffffffu, p, 2);
        p += __shfl_xor_sync(0xffffffffu, p, 1);
        if ((t & 15) == 0) {
            float lg = (p > 0.f) ? p : 0.2f * p;     // leaky_relu 0.2
            s_logit[e][t >> 4] = (s_valid[e] > 0.f) ? lg : -1e9f;
        }
    }
    __syncthreads();
    // per-head softmax over the 30 incoming edges
    if (t < 8) {
        float mx = -1e30f;
        for (int e = 0; e < KK; e++) mx = fmaxf(mx, s_logit[e][t]);
        float den = 0.f;
        for (int e = 0; e < KK; e++) {
            float ex = __expf(s_logit[e][t] - mx) * s_valid[e];
            s_alpha[e][t] = ex; den += ex;
        }
        float inv = 1.f / (den + 1e-9f);
        for (int e = 0; e < KK; e++) s_alpha[e][t] *= inv;
    }
    __syncthreads();
    // weighted value aggregation (rotation cancelled -> pure gather-FMA)
    int h = (t & 63) >> 3;
    float a0 = 0.f, a1 = 0.f;
#pragma unroll
    for (int e = 0; e < KK; e++) {
        const float* vp = g_Vnode + (size_t)s_src[e] * 256;
        float al = s_alpha[e][h];
        a0 = fmaf(al, vp[t],       a0);
        a1 = fmaf(al, vp[t + 128], a1);
    }
    s_agg[t] = a0; s_agg[t + 128] = a1;
    __syncthreads();
    // y = agg @ W_o
    int r = t >> 5, o = t & 31;
    float y = 0.f;
#pragma unroll
    for (int cc = 0; cc < 64; cc++)
        y = fmaf(s_agg[r * 64 + cc], Wo[cc * 32 + o], y);
    s_y[t] = y;
    __syncthreads();
    if (t < 32) {
        float g = 0.f;
#pragma unroll
        for (int j = 0; j < 32; j++) g = fmaf(s_y[j], Wg[j * 32 + t], g);
        s_gate[t] = g / (1.f + __expf(-g));          // silu gate
    }
    __syncthreads();
    float oo = 0.f;
#pragma unroll
    for (int j = 0; j < 32; j++)
        oo = fmaf(s_y[r * 32 + j] * s_gate[j], W2[j * 32 + o], oo);
    out[n * 128 + t] = oo;
}

// ---------------- launch ----------------
extern "C" void kernel_launch(void* const* d_in, const int* in_sizes, int n_in,
                              void* d_out, int out_size)
{
    const float* rots     = (const float*)d_in[0];
    const float* trans    = (const float*)d_in[1];
    const float* node_emb = (const float*)d_in[2];
    // d_in[3] = batch (unused)
    const unsigned char* xm = (const unsigned char*)d_in[4];
    const unsigned char* nm = (const unsigned char*)d_in[5];
    const float* Wa = (const float*)d_in[6];
    const float* av = (const float*)d_in[7];
    const float* Wv = (const float*)d_in[8];
    const float* Wo = (const float*)d_in[9];
    const float* Wg = (const float*)d_in[10];
    const float* W2 = (const float*)d_in[11];
    float* out = (float*)d_out;

    k_posA<<<1023, 128>>>(Wa, xm);
    k_knn <<<NN / 4, 128>>>(trans);
    k_node<<<NN / 8, 128>>>(rots, node_emb, xm, nm, Wa, Wv);
    k_main<<<NN, 128>>>(Wa, av, Wo, Wg, W2, out);
}